// round 9
// baseline (speedup 1.0000x reference)
#include <cuda_runtime.h>
#include <cuda_bf16.h>
#include <mma.h>
#include <math.h>

using namespace nvcuda;

// ---------------- problem dims ----------------
#define BQ 8
#define NQ 896
#define MQ 512
#define ENF 3072
#define AAD 1280
#define HH 32
#define DD 64
#define INNER 2048
#define CTXD 256

#define SEQ_ROWS (BQ * NQ)   // 7168
#define AA_ROWS  (BQ * MQ)   // 4096

// ---------------- scratch (__device__ globals; no allocs allowed) ----------------
__device__ __nv_bfloat16 g_seq_e[(size_t)SEQ_ROWS * ENF];       // [row][k]
__device__ __nv_bfloat16 g_aa_e[(size_t)AA_ROWS * AAD];         // [row][k]
__device__ __nv_bfloat16 g_seq_w[(size_t)ENF * INNER];          // [k][n]
__device__ __nv_bfloat16 g_aa_w[(size_t)AAD * INNER];           // [k][n]
__device__ __nv_bfloat16 g_seq_lat[(size_t)BQ * HH * NQ * DD];  // [b][h][n][d]
__device__ __nv_bfloat16 g_aa_lat[(size_t)BQ * HH * MQ * DD];   // [b][h][j][d]
__device__ float g_inter[(size_t)BQ * NQ * HH];                 // [b][n][h]
__device__ float g_v[BQ * HH];
__device__ int g_mask_mode;
__device__ unsigned char g_mask[BQ * MQ];

// ---------------- helpers ----------------
__device__ __forceinline__ void cp_async16(void* smem_dst, const void* gsrc) {
    unsigned int s = (unsigned int)__cvta_generic_to_shared(smem_dst);
    asm volatile("cp.async.cg.shared.global [%0], [%1], 16;\n" :: "r"(s), "l"(gsrc));
}
__device__ __forceinline__ void cp_commit() { asm volatile("cp.async.commit_group;\n"); }
template <int N>
__device__ __forceinline__ void cp_wait() { asm volatile("cp.async.wait_group %0;\n" :: "n"(N)); }

// ---------------- kernel 0: fused f32 -> bf16 convert (all 4 tensors) ----------------
#define CVT_S0 (SEQ_ROWS * ENF / 4)   // 5505024
#define CVT_S1 (AA_ROWS * AAD / 4)    // 1310720
#define CVT_S2 (ENF * INNER / 4)      // 1572864
#define CVT_S3 (AAD * INNER / 4)      // 655360
#define CVT_TOT (CVT_S0 + CVT_S1 + CVT_S2 + CVT_S3)

__global__ void cvt_all(const float4* __restrict__ s0, const float4* __restrict__ s1,
                        const float4* __restrict__ s2, const float4* __restrict__ s3) {
    int i = blockIdx.x * blockDim.x + threadIdx.x;
    if (i >= CVT_TOT) return;
    const float4* src;
    uint2* dst;
    int off;
    if (i < CVT_S0) {
        src = s0; dst = reinterpret_cast<uint2*>(g_seq_e); off = i;
    } else if (i < CVT_S0 + CVT_S1) {
        src = s1; dst = reinterpret_cast<uint2*>(g_aa_e); off = i - CVT_S0;
    } else if (i < CVT_S0 + CVT_S1 + CVT_S2) {
        src = s2; dst = reinterpret_cast<uint2*>(g_seq_w); off = i - CVT_S0 - CVT_S1;
    } else {
        src = s3; dst = reinterpret_cast<uint2*>(g_aa_w); off = i - CVT_S0 - CVT_S1 - CVT_S2;
    }
    float4 f = src[off];
    __nv_bfloat162 lo = __floats2bfloat162_rn(f.x, f.y);
    __nv_bfloat162 hi = __floats2bfloat162_rn(f.z, f.w);
    uint2 u;
    u.x = *reinterpret_cast<unsigned int*>(&lo);
    u.y = *reinterpret_cast<unsigned int*>(&hi);
    dst[off] = u;
}

// ---------------- mask dtype detect + canonicalize ----------------
__global__ void mask_detect(const unsigned int* __restrict__ m) {
    if (threadIdx.x != 0 || blockIdx.x != 0) return;
    int mode = 1;  // default int32
    for (int i = 0; i < 1024; i++) {
        unsigned int v = m[i];
        if (v == 0x3F800000u) { mode = 2; break; }
        if (v > 1u) { mode = 0; break; }
    }
    g_mask_mode = mode;
}
__global__ void mask_canon(const void* __restrict__ src) {
    int i = blockIdx.x * blockDim.x + threadIdx.x;
    if (i >= BQ * MQ) return;
    int mode = g_mask_mode;
    unsigned char v;
    if (mode == 0)      v = ((const unsigned char*)src)[i] ? 1 : 0;
    else if (mode == 1) v = (((const int*)src)[i] != 0) ? 1 : 0;
    else                v = (((const float*)src)[i] != 0.0f) ? 1 : 0;
    g_mask[i] = v;
}

// ---------------- projection GEMM (wmma): 128x256 block, 64x64 warp, BK=16, 4-stage ----------------
#define PT_M 128
#define PT_N 256
#define PT_BK 16
#define NSTG 4
#define ALD 24                        // halves per A row (16 + 8 pad)
#define BLD 264                       // halves per B row (256 + 8 pad)
#define A_STG_H (PT_M * ALD)          // 3072 halves (6144 B)
#define B_STG_H (PT_BK * BLD)         // 4224 halves (8448 B)
#define PROJ_SMEM_BYTES ((NSTG * A_STG_H + NSTG * B_STG_H) * 2)   // 58368
#define CLD 68                        // f32 epilogue row stride

__global__ void __launch_bounds__(256, 1)
proj_wmma_kernel(const float* __restrict__ bias, int which)   // 0=seq, 1=aa
{
    extern __shared__ __align__(16) __nv_bfloat16 smem[];
    __nv_bfloat16* Asm = smem;                       // [NSTG][128][ALD]
    __nv_bfloat16* Bsm = smem + NSTG * A_STG_H;      // [NSTG][16][BLD]
    float* Cs = reinterpret_cast<float*>(smem);      // [128][CLD] overlay (epilogue)
    __shared__ float s_bias[PT_N];

    const __nv_bfloat16* A = which ? g_aa_e : g_seq_e;
    const __nv_bfloat16* W = which ? g_aa_w : g_seq_w;
    __nv_bfloat16* outLat  = which ? g_aa_lat : g_seq_lat;
    const int K   = which ? AAD : ENF;
    const int rpb = which ? MQ : NQ;
    const int nK  = K / PT_BK;

    const int tid = threadIdx.x;
    const int wid = tid >> 5;
    const int warp_m = wid >> 2;   // 0..1 -> rows 64*warp_m
    const int warp_n = wid & 3;    // 0..3 -> cols 64*warp_n
    const int row0 = blockIdx.x * PT_M;
    const int col0 = blockIdx.y * PT_N;

    // 256 threads cover exactly PT_N=256 bias values (FIX: was OOB dual-write)
    s_bias[tid] = bias[col0 + tid];

    wmma::fragment<wmma::accumulator, 16, 16, 16, float> acc[4][4];
#pragma unroll
    for (int i = 0; i < 4; i++)
#pragma unroll
        for (int j = 0; j < 4; j++) wmma::fill_fragment(acc[i][j], 0.0f);

    // per-thread load coords
    const int ar = tid >> 1, ac = tid & 1;          // A: 128 rows x 2 16B-chunks
    const int br0 = tid >> 5, bc = tid & 31;        // B: rows tid>>5 and +8, 32 16B-chunks

    auto load_stage = [&](int kt, int s) {
        __nv_bfloat16* As = Asm + s * A_STG_H;
        __nv_bfloat16* Bs = Bsm + s * B_STG_H;
        const size_t kb = (size_t)kt * PT_BK;
        cp_async16(As + ar * ALD + ac * 8, A + (size_t)(row0 + ar) * K + kb + ac * 8);
#pragma unroll
        for (int i = 0; i < 2; i++) {
            int r = br0 + i * 8;
            cp_async16(Bs + r * BLD + bc * 8, W + (kb + r) * INNER + col0 + bc * 8);
        }
    };

    load_stage(0, 0); cp_commit();
    load_stage(1, 1); cp_commit();

    for (int kt = 0; kt < nK; kt++) {
        const int s = kt & (NSTG - 1);
        // FIX: tail-aware wait depth; empty commit groups give no backpressure
        if (kt + 2 < nK) {
            load_stage(kt + 2, (kt + 2) & (NSTG - 1));
            cp_commit();
            cp_wait<2>();
        } else if (kt + 1 < nK) {
            cp_wait<1>();
        } else {
            cp_wait<0>();
        }
        __syncthreads();

        const __nv_bfloat16* As = Asm + s * A_STG_H;
        const __nv_bfloat16* Bs = Bsm + s * B_STG_H;

        wmma::fragment<wmma::matrix_b, 16, 16, 16, __nv_bfloat16, wmma::row_major> bf[4];
#pragma unroll
        for (int j = 0; j < 4; j++)
            wmma::load_matrix_sync(bf[j], Bs + warp_n * 64 + j * 16, BLD);
#pragma unroll
        for (int i = 0; i < 4; i++) {
            wmma::fragment<wmma::matrix_a, 16, 16, 16, __nv_bfloat16, wmma::row_major> af;
            wmma::load_matrix_sync(af, As + (warp_m * 64 + i * 16) * ALD, ALD);
#pragma unroll
            for (int j = 0; j < 4; j++)
                wmma::mma_sync(acc[i][j], af, bf[j], acc[i][j]);
        }
    }
    __syncthreads();

    // ---- epilogue: 4 passes, one head (64 cols) per pass ----
    for (int p = 0; p < 4; p++) {
        if (warp_n == p) {
#pragma unroll
            for (int i = 0; i < 4; i++)
#pragma unroll
                for (int j = 0; j < 4; j++)
                    wmma::store_matrix_sync(Cs + (warp_m * 64 + i * 16) * CLD + j * 16,
                                            acc[i][j], CLD, wmma::mem_row_major);
        }
        __syncthreads();

        int r = tid >> 1, half = tid & 1;   // 2 threads per row, 32 cols each
        const float* crow = Cs + r * CLD + half * 32;
        const float* brow = s_bias + p * 64 + half * 32;
        float ss = 0.f;
#pragma unroll
        for (int c = 0; c < 32; c++) {
            float t = crow[c] + brow[c];
            ss = fmaf(t, t, ss);
        }
        ss += __shfl_xor_sync(0xffffffffu, ss, 1);
        float scale = 1.f / fmaxf(sqrtf(ss), 1e-12f);

        int gr = row0 + r;
        int b = gr / rpb, n = gr % rpb;
        int h = (col0 >> 6) + p;
        __nv_bfloat16* op = outLat + ((size_t)(b * HH + h) * rpb + n) * DD + half * 32;
#pragma unroll
        for (int c8 = 0; c8 < 32; c8 += 8) {
            unsigned int w[4];
#pragma unroll
            for (int t2 = 0; t2 < 4; t2++) {
                float v0 = (crow[c8 + 2 * t2] + brow[c8 + 2 * t2]) * scale;
                float v1 = (crow[c8 + 2 * t2 + 1] + brow[c8 + 2 * t2 + 1]) * scale;
                __nv_bfloat162 p2 = __floats2bfloat162_rn(v0, v1);
                w[t2] = *reinterpret_cast<unsigned int*>(&p2);
            }
            *reinterpret_cast<uint4*>(op + c8) = *reinterpret_cast<uint4*>(w);
        }
        __syncthreads();
    }
}

// ---------------- kernel 3: interaction scores + masked online logsumexp ----------------
#define ILDS 72
#define ILDC 68

__global__ void __launch_bounds__(256, 2)
inter_kernel()
{
    __shared__ __nv_bfloat16 Sseq[64 * ILDS];
    __shared__ __nv_bfloat16 Saa[64 * ILDS];
    __shared__ float Csm[64 * ILDC];
    __shared__ float m_run[64], s_run[64];
    __shared__ unsigned char msk[64];

    const int tid = threadIdx.x;
    const int wid = tid >> 5;
    const int itile = blockIdx.x;
    const int bh = blockIdx.y;
    const int b = bh >> 5;

    const __nv_bfloat16* seqp = g_seq_lat + (size_t)bh * NQ * DD + (size_t)itile * 64 * DD;
    const __nv_bfloat16* aap = g_aa_lat + (size_t)bh * MQ * DD;
    const unsigned char* mp = g_mask + b * MQ;

#pragma unroll
    for (int i = 0; i < 2; i++) {
        int idx = tid + i * 256;
        int r = idx >> 3, dq = idx & 7;
        *reinterpret_cast<uint4*>(Sseq + r * ILDS + dq * 8) =
            *reinterpret_cast<const uint4*>(seqp + r * DD + dq * 8);
    }
    if (tid < 64) { m_run[tid] = -INFINITY; s_run[tid] = 0.f; }

    const int warp_m = wid & 3;
    const int warp_n = wid >> 2;

    for (int jc = 0; jc < 8; jc++) {
        __syncthreads();
#pragma unroll
        for (int i = 0; i < 2; i++) {
            int idx = tid + i * 256;
            int r = idx >> 3, dq = idx & 7;
            *reinterpret_cast<uint4*>(Saa + r * ILDS + dq * 8) =
                *reinterpret_cast<const uint4*>(aap + (size_t)(jc * 64 + r) * DD + dq * 8);
        }
        if (tid < 64) msk[tid] = mp[jc * 64 + tid];
        __syncthreads();

        wmma::fragment<wmma::accumulator, 16, 16, 16, float> acc[2];
        wmma::fill_fragment(acc[0], 0.f);
        wmma::fill_fragment(acc[1], 0.f);
#pragma unroll
        for (int kk = 0; kk < 64; kk += 16) {
            wmma::fragment<wmma::matrix_a, 16, 16, 16, __nv_bfloat16, wmma::row_major> af;
            wmma::load_matrix_sync(af, Sseq + (warp_m * 16) * ILDS + kk, ILDS);
#pragma unroll
            for (int j = 0; j < 2; j++) {
                wmma::fragment<wmma::matrix_b, 16, 16, 16, __nv_bfloat16, wmma::col_major> bfg;
                wmma::load_matrix_sync(bfg, Saa + (warp_n * 32 + j * 16) * ILDS + kk, ILDS);
                wmma::mma_sync(acc[j], af, bfg, acc[j]);
            }
        }
        wmma::store_matrix_sync(Csm + (warp_m * 16) * ILDC + warp_n * 32, acc[0], ILDC, wmma::mem_row_major);
        wmma::store_matrix_sync(Csm + (warp_m * 16) * ILDC + warp_n * 32 + 16, acc[1], ILDC, wmma::mem_row_major);
        __syncthreads();

        int r = tid >> 2, part = tid & 3;
        float vals[16];
        float lmax = -INFINITY;
#pragma unroll
        for (int c = 0; c < 16; c++) {
            int j = part * 16 + c;
            float vv = msk[j] ? -3.402823466e38f : Csm[r * ILDC + j];
            vals[c] = vv;
            lmax = fmaxf(lmax, vv);
        }
        lmax = fmaxf(lmax, __shfl_xor_sync(0xffffffffu, lmax, 1));
        lmax = fmaxf(lmax, __shfl_xor_sync(0xffffffffu, lmax, 2));
        float m_old = m_run[r];
        float m_new = fmaxf(m_old, lmax);
        float lsum = 0.f;
#pragma unroll
        for (int c = 0; c < 16; c++) lsum += expf(vals[c] - m_new);
        lsum += __shfl_xor_sync(0xffffffffu, lsum, 1);
        lsum += __shfl_xor_sync(0xffffffffu, lsum, 2);
        if (part == 0) {
            s_run[r] = s_run[r] * expf(m_old - m_new) + lsum;
            m_run[r] = m_new;
        }
    }
    __syncthreads();

    if (tid < 64) {
        int i = itile * 64 + tid;
        g_inter[((size_t)b * NQ + i) * HH + (bh & 31)] = m_run[tid] + logf(s_run[tid]);
    }
}

// ---------------- kernel 4a: fold gating + pred_w into v[b][h] ----------------
__global__ void __launch_bounds__(1024)
gate_kernel(const float* __restrict__ ctx, const float* __restrict__ ctx_w,
            const float* __restrict__ ctx_b, const float* __restrict__ tlw,
            const float* __restrict__ pred_w)
{
    int b = blockIdx.x;
    int h = threadIdx.x >> 5, hp = threadIdx.x & 31;
    const float* cb = ctx + b * CTXD;
    int col = h * 32 + hp;
    float acc = 0.f;
#pragma unroll 8
    for (int k = 0; k < CTXD; k++) acc += cb[k] * ctx_w[k * (HH * HH) + col];
    float g = 1.f / (1.f + expf(-(acc + ctx_b[col])));
    float val = tlw[h * 32 + hp] * g * pred_w[hp];
#pragma unroll
    for (int o = 16; o; o >>= 1) val += __shfl_xor_sync(0xffffffffu, val, o);
    if (hp == 0) g_v[b * HH + h] = val;
}

// ---------------- kernel 4b: pred = softplus(inter . v + pred_b) ----------------
__global__ void pred_kernel(const float* __restrict__ pred_b, float* __restrict__ out)
{
    int idx = blockIdx.x * blockDim.x + threadIdx.x;
    if (idx >= SEQ_ROWS) return;
    int b = idx / NQ;
    const float* ip = g_inter + (size_t)idx * HH;
    const float* vp = g_v + b * HH;
    float x = pred_b[0];
#pragma unroll
    for (int hq = 0; hq < HH; hq++) x += ip[hq] * vp[hq];
    out[idx] = fmaxf(x, 0.f) + log1pf(expf(-fabsf(x)));
}

// ---------------- launch ----------------
extern "C" void kernel_launch(void* const* d_in, const int* in_sizes, int n_in,
                              void* d_out, int out_size)
{
    const float* seq_embed = (const float*)d_in[0];
    const float* aa_embed  = (const float*)d_in[1];
    const float* ctx       = (const float*)d_in[2];
    const float* seq_b     = (const float*)d_in[4];
    const float* aa_b      = (const float*)d_in[6];
    const float* tlw       = (const float*)d_in[7];
    const float* ctx_w     = (const float*)d_in[8];
    const float* ctx_b     = (const float*)d_in[9];
    const float* pred_w    = (const float*)d_in[10];
    const float* pred_b    = (const float*)d_in[11];
    float* out = (float*)d_out;

    cudaFuncSetAttribute(proj_wmma_kernel, cudaFuncAttributeMaxDynamicSharedMemorySize,
                         PROJ_SMEM_BYTES);

    // 0) fused convert of all inputs/weights to bf16
    cvt_all<<<(CVT_TOT + 255) / 256, 256>>>((const float4*)seq_embed, (const float4*)aa_embed,
                                            (const float4*)d_in[3], (const float4*)d_in[5]);

    // 0b) mask dtype detect + canonicalize
    mask_detect<<<1, 1>>>((const unsigned int*)d_in[12]);
    mask_canon<<<(BQ * MQ + 255) / 256, 256>>>(d_in[12]);

    // 1) seq projection + l2norm
    proj_wmma_kernel<<<dim3(SEQ_ROWS / PT_M, INNER / PT_N), 256, PROJ_SMEM_BYTES>>>(seq_b, 0);
    // 2) aa projection + l2norm
    proj_wmma_kernel<<<dim3(AA_ROWS / PT_M, INNER / PT_N), 256, PROJ_SMEM_BYTES>>>(aa_b, 1);

    // 3) interaction + masked logsumexp
    inter_kernel<<<dim3(NQ / 64, BQ * HH), 256>>>();

    // 4) gating fold + prediction
    gate_kernel<<<BQ, 1024>>>(ctx, ctx_w, ctx_b, tlw, pred_w);
    pred_kernel<<<(SEQ_ROWS + 255) / 256, 256>>>(pred_b, out);
}

// round 12
// speedup vs baseline: 1.3015x; 1.3015x over previous
#include <cuda_runtime.h>
#include <cuda_bf16.h>
#include <math.h>

// ---------------- problem dims ----------------
#define BQ 8
#define NQ 896
#define MQ 512
#define ENF 3072
#define AAD 1280
#define HH 32
#define DD 64
#define INNER 2048
#define CTXD 256

#define SEQ_ROWS (BQ * NQ)   // 7168
#define AA_ROWS  (BQ * MQ)   // 4096

// ---------------- scratch ----------------
__device__ __nv_bfloat16 g_seq_e[(size_t)SEQ_ROWS * ENF];       // [row][k]
__device__ __nv_bfloat16 g_aa_e[(size_t)AA_ROWS * AAD];         // [row][k]
__device__ __nv_bfloat16 g_seq_w[(size_t)ENF * INNER];          // [k][n]
__device__ __nv_bfloat16 g_aa_w[(size_t)AAD * INNER];           // [k][n]
__device__ __nv_bfloat16 g_seq_lat[(size_t)BQ * HH * NQ * DD];  // [b][h][n][d]
__device__ __nv_bfloat16 g_aa_lat[(size_t)BQ * HH * MQ * DD];   // [b][h][j][d]
__device__ float g_inter[(size_t)BQ * NQ * HH];                 // [b][n][h]
__device__ float g_v[BQ * HH];
__device__ int g_mask_mode;
__device__ unsigned char g_mask[BQ * MQ];

// ---------------- helpers ----------------
__device__ __forceinline__ void cp_async16(void* smem_dst, const void* gsrc) {
    unsigned int s = (unsigned int)__cvta_generic_to_shared(smem_dst);
    asm volatile("cp.async.cg.shared.global [%0], [%1], 16;\n" :: "r"(s), "l"(gsrc));
}
__device__ __forceinline__ void cp_async4(void* smem_dst, const void* gsrc) {
    unsigned int s = (unsigned int)__cvta_generic_to_shared(smem_dst);
    asm volatile("cp.async.ca.shared.global [%0], [%1], 4;\n" :: "r"(s), "l"(gsrc));
}
__device__ __forceinline__ void cp_commit() { asm volatile("cp.async.commit_group;\n"); }
template <int N>
__device__ __forceinline__ void cp_wait() { asm volatile("cp.async.wait_group %0;\n" :: "n"(N)); }
__device__ __forceinline__ unsigned int smem_u32(const void* p) {
    return (unsigned int)__cvta_generic_to_shared(p);
}

__device__ __forceinline__ void ldsm_x4(unsigned* r, unsigned addr) {
    asm volatile("ldmatrix.sync.aligned.m8n8.x4.shared.b16 {%0,%1,%2,%3}, [%4];"
                 : "=r"(r[0]), "=r"(r[1]), "=r"(r[2]), "=r"(r[3]) : "r"(addr));
}
__device__ __forceinline__ void ldsm_x4_t(unsigned* r, unsigned addr) {
    asm volatile("ldmatrix.sync.aligned.m8n8.x4.trans.shared.b16 {%0,%1,%2,%3}, [%4];"
                 : "=r"(r[0]), "=r"(r[1]), "=r"(r[2]), "=r"(r[3]) : "r"(addr));
}
__device__ __forceinline__ void mma_bf16(float* c, const unsigned* a, const unsigned* b) {
    asm volatile("mma.sync.aligned.m16n8k16.row.col.f32.bf16.bf16.f32 "
                 "{%0,%1,%2,%3}, {%4,%5,%6,%7}, {%8,%9}, {%0,%1,%2,%3};\n"
                 : "+f"(c[0]), "+f"(c[1]), "+f"(c[2]), "+f"(c[3])
                 : "r"(a[0]), "r"(a[1]), "r"(a[2]), "r"(a[3]), "r"(b[0]), "r"(b[1]));
}
__device__ __forceinline__ void mma_bf16_2(float* c, const unsigned* a,
                                           unsigned b0, unsigned b1) {
    asm volatile("mma.sync.aligned.m16n8k16.row.col.f32.bf16.bf16.f32 "
                 "{%0,%1,%2,%3}, {%4,%5,%6,%7}, {%8,%9}, {%0,%1,%2,%3};\n"
                 : "+f"(c[0]), "+f"(c[1]), "+f"(c[2]), "+f"(c[3])
                 : "r"(a[0]), "r"(a[1]), "r"(a[2]), "r"(a[3]), "r"(b0), "r"(b1));
}

// ---------------- kernel 0: fused f32 -> bf16 convert ----------------
#define CVT_S0 (SEQ_ROWS * ENF / 4)
#define CVT_S1 (AA_ROWS * AAD / 4)
#define CVT_S2 (ENF * INNER / 4)
#define CVT_S3 (AAD * INNER / 4)
#define CVT_TOT (CVT_S0 + CVT_S1 + CVT_S2 + CVT_S3)

__global__ void cvt_all(const float4* __restrict__ s0, const float4* __restrict__ s1,
                        const float4* __restrict__ s2, const float4* __restrict__ s3) {
    int i = blockIdx.x * blockDim.x + threadIdx.x;
    if (i >= CVT_TOT) return;
    const float4* src;
    uint2* dst;
    int off;
    if (i < CVT_S0) {
        src = s0; dst = reinterpret_cast<uint2*>(g_seq_e); off = i;
    } else if (i < CVT_S0 + CVT_S1) {
        src = s1; dst = reinterpret_cast<uint2*>(g_aa_e); off = i - CVT_S0;
    } else if (i < CVT_S0 + CVT_S1 + CVT_S2) {
        src = s2; dst = reinterpret_cast<uint2*>(g_seq_w); off = i - CVT_S0 - CVT_S1;
    } else {
        src = s3; dst = reinterpret_cast<uint2*>(g_aa_w); off = i - CVT_S0 - CVT_S1 - CVT_S2;
    }
    float4 f = src[off];
    __nv_bfloat162 lo = __floats2bfloat162_rn(f.x, f.y);
    __nv_bfloat162 hi = __floats2bfloat162_rn(f.z, f.w);
    uint2 u;
    u.x = *reinterpret_cast<unsigned int*>(&lo);
    u.y = *reinterpret_cast<unsigned int*>(&hi);
    dst[off] = u;
}

// ---------------- mask dtype detect + canonicalize ----------------
__global__ void mask_detect(const unsigned int* __restrict__ m) {
    if (threadIdx.x != 0 || blockIdx.x != 0) return;
    int mode = 1;
    for (int i = 0; i < 1024; i++) {
        unsigned int v = m[i];
        if (v == 0x3F800000u) { mode = 2; break; }
        if (v > 1u) { mode = 0; break; }
    }
    g_mask_mode = mode;
}
__global__ void mask_canon(const void* __restrict__ src) {
    int i = blockIdx.x * blockDim.x + threadIdx.x;
    if (i >= BQ * MQ) return;
    int mode = g_mask_mode;
    unsigned char v;
    if (mode == 0)      v = ((const unsigned char*)src)[i] ? 1 : 0;
    else if (mode == 1) v = (((const int*)src)[i] != 0) ? 1 : 0;
    else                v = (((const float*)src)[i] != 0.0f) ? 1 : 0;
    g_mask[i] = v;
}

// ---------------- projection GEMM (raw mma): 128x256 block, 64x64 warp, BK=32, 4-stage ----------------
#define PT_M 128
#define PT_N 256
#define PT_BK 32
#define NSTG 4
#define ALD 40                         // halves per A row (32 + 8 pad)
#define BLD 264                        // halves per B row (256 + 8 pad)
#define A_STG_H (PT_M * ALD)
#define B_STG_H (PT_BK * BLD)
#define A_STG_B (A_STG_H * 2)
#define B_STG_B (B_STG_H * 2)
#define PROJ_SMEM_BYTES (NSTG * (A_STG_B + B_STG_B))   // 108544
#define CLD 68

__global__ void __launch_bounds__(256, 1)
proj_mma_kernel(const float* __restrict__ bias, int which)   // 0=seq, 1=aa
{
    extern __shared__ __align__(16) __nv_bfloat16 smem[];
    __nv_bfloat16* Asm = smem;                          // [NSTG][128][ALD]
    __nv_bfloat16* Bsm = smem + NSTG * A_STG_H;         // [NSTG][32][BLD]
    float* Cs = reinterpret_cast<float*>(smem);         // [128][CLD] overlay
    __shared__ float s_bias[PT_N];

    const __nv_bfloat16* A = which ? g_aa_e : g_seq_e;
    const __nv_bfloat16* W = which ? g_aa_w : g_seq_w;
    __nv_bfloat16* outLat  = which ? g_aa_lat : g_seq_lat;
    const int K   = which ? AAD : ENF;
    const int rpb = which ? MQ : NQ;
    const int nK  = K / PT_BK;

    const int tid = threadIdx.x;
    const int wid = tid >> 5;
    const int lane = tid & 31;
    const int warp_m = wid >> 2;
    const int warp_n = wid & 3;
    const int row0 = blockIdx.x * PT_M;
    const int col0 = blockIdx.y * PT_N;

    s_bias[tid] = bias[col0 + tid];

    float c[4][8][4];
#pragma unroll
    for (int mi = 0; mi < 4; mi++)
#pragma unroll
        for (int ni = 0; ni < 8; ni++)
#pragma unroll
            for (int e = 0; e < 4; e++) c[mi][ni][e] = 0.f;

    const int ar = tid >> 1, ac = (tid & 1) * 16;
    const int br = tid >> 3, bc = (tid & 7) * 32;

    const unsigned smem_b32 = smem_u32(smem);
    const unsigned B_base = smem_b32 + NSTG * A_STG_B;

    auto load_stage = [&](int kt, int s) {
        __nv_bfloat16* As = Asm + s * A_STG_H;
        __nv_bfloat16* Bs = Bsm + s * B_STG_H;
        const size_t kb = (size_t)kt * PT_BK;
        cp_async16(As + ar * ALD + ac,     A + (size_t)(row0 + ar) * K + kb + ac);
        cp_async16(As + ar * ALD + ac + 8, A + (size_t)(row0 + ar) * K + kb + ac + 8);
#pragma unroll
        for (int i = 0; i < 4; i++)
            cp_async16(Bs + br * BLD + bc + i * 8,
                       W + (kb + br) * INNER + col0 + bc + i * 8);
    };

    load_stage(0, 0); cp_commit();
    load_stage(1, 1); cp_commit();

    const int lr = lane & 15;
    const int ko = (lane >> 4) * 8;

    for (int kt = 0; kt < nK; kt++) {
        const int s = kt & (NSTG - 1);
        if (kt + 2 < nK) {
            load_stage(kt + 2, (kt + 2) & (NSTG - 1));
            cp_commit();
            cp_wait<2>();
        } else if (kt + 1 < nK) {
            cp_wait<1>();
        } else {
            cp_wait<0>();
        }
        __syncthreads();

        const unsigned As_u = smem_b32 + s * A_STG_B;
        const unsigned Bs_u = B_base + s * B_STG_B;

#pragma unroll
        for (int kk8 = 0; kk8 < 2; kk8++) {
            unsigned af[4][4];
#pragma unroll
            for (int mi = 0; mi < 4; mi++)
                ldsm_x4(af[mi], As_u + ((warp_m * 64 + mi * 16 + lr) * ALD + kk8 * 16 + ko) * 2);
            unsigned bf4[4][4];
#pragma unroll
            for (int np = 0; np < 4; np++)
                ldsm_x4_t(bf4[np], Bs_u + ((kk8 * 16 + lr) * BLD + warp_n * 64 + np * 16 + ko) * 2);
            // trans delivery: {r0,r1} = (k0-15, n0-7), {r2,r3} = (k0-15, n8-15)
#pragma unroll
            for (int mi = 0; mi < 4; mi++)
#pragma unroll
                for (int np = 0; np < 4; np++) {
                    mma_bf16(c[mi][np * 2],     af[mi], &bf4[np][0]);
                    mma_bf16(c[mi][np * 2 + 1], af[mi], &bf4[np][2]);
                }
        }
    }
    __syncthreads();

    // ---- epilogue: 4 passes, one head (64 cols) per pass ----
    const int g = lane >> 2, t2 = (lane & 3) * 2;
    for (int p = 0; p < 4; p++) {
        if (warp_n == p) {
#pragma unroll
            for (int mi = 0; mi < 4; mi++)
#pragma unroll
                for (int ni = 0; ni < 8; ni++) {
                    int rb = warp_m * 64 + mi * 16;
                    int cb = ni * 8 + t2;
                    Cs[(rb + g) * CLD + cb]         = c[mi][ni][0];
                    Cs[(rb + g) * CLD + cb + 1]     = c[mi][ni][1];
                    Cs[(rb + g + 8) * CLD + cb]     = c[mi][ni][2];
                    Cs[(rb + g + 8) * CLD + cb + 1] = c[mi][ni][3];
                }
        }
        __syncthreads();

        int r = tid >> 1, half = tid & 1;
        const float* crow = Cs + r * CLD + half * 32;
        const float* brow = s_bias + p * 64 + half * 32;
        float ss = 0.f;
#pragma unroll
        for (int cc = 0; cc < 32; cc++) {
            float tt = crow[cc] + brow[cc];
            ss = fmaf(tt, tt, ss);
        }
        ss += __shfl_xor_sync(0xffffffffu, ss, 1);
        float scale = 1.f / fmaxf(sqrtf(ss), 1e-12f);

        int gr = row0 + r;
        int b = gr / rpb, n = gr % rpb;
        int h = (col0 >> 6) + p;
        __nv_bfloat16* op = outLat + ((size_t)(b * HH + h) * rpb + n) * DD + half * 32;
#pragma unroll
        for (int c8 = 0; c8 < 32; c8 += 8) {
            unsigned int w[4];
#pragma unroll
            for (int q = 0; q < 4; q++) {
                float v0 = (crow[c8 + 2 * q] + brow[c8 + 2 * q]) * scale;
                float v1 = (crow[c8 + 2 * q + 1] + brow[c8 + 2 * q + 1]) * scale;
                __nv_bfloat162 p2 = __floats2bfloat162_rn(v0, v1);
                w[q] = *reinterpret_cast<unsigned int*>(&p2);
            }
            *reinterpret_cast<uint4*>(op + c8) = *reinterpret_cast<uint4*>(w);
        }
        __syncthreads();
    }
}

// ---------------- interaction (raw mma, reg-resident lse): 128 i-rows/block ----------------
#define ISD 72

__global__ void __launch_bounds__(256, 2)
inter_kernel()
{
    __shared__ __align__(16) __nv_bfloat16 Sseq[128 * ISD];
    __shared__ __align__(16) __nv_bfloat16 Saa[2][64 * ISD];
    __shared__ unsigned char Smask[2][64];

    const int tid = threadIdx.x;
    const int lane = tid & 31;
    const int w = tid >> 5;
    const int itile = blockIdx.x;
    const int bh = blockIdx.y;
    const int b = bh >> 5, h = bh & 31;

    const __nv_bfloat16* seqp = g_seq_lat + (size_t)bh * NQ * DD + (size_t)itile * 128 * DD;
    const __nv_bfloat16* aap = g_aa_lat + (size_t)bh * MQ * DD;
    const unsigned char* mp = g_mask + b * MQ;

#pragma unroll
    for (int i = 0; i < 4; i++) {
        int idx = tid + i * 256;
        int r = idx >> 3, dq = idx & 7;
        cp_async16(Sseq + r * ISD + dq * 8, seqp + r * DD + dq * 8);
    }
#pragma unroll
    for (int i = 0; i < 2; i++) {
        int idx = tid + i * 256;
        int r = idx >> 3, dq = idx & 7;
        cp_async16(&Saa[0][r * ISD + dq * 8], aap + (size_t)r * DD + dq * 8);
    }
    if (tid < 16) cp_async4(&Smask[0][tid * 4], mp + tid * 4);
    cp_commit();
    cp_wait<0>();
    __syncthreads();

    const unsigned seq_u = smem_u32(Sseq);
    const unsigned aa_u = smem_u32(&Saa[0][0]);
    const int lr = lane & 15, ko = (lane >> 4) * 8;
    unsigned a[4][4];
#pragma unroll
    for (int kks = 0; kks < 4; kks++)
        ldsm_x4(a[kks], seq_u + ((w * 16 + lr) * ISD + kks * 16 + ko) * 2);

    {
#pragma unroll
        for (int i = 0; i < 2; i++) {
            int idx = tid + i * 256;
            int r = idx >> 3, dq = idx & 7;
            cp_async16(&Saa[1][r * ISD + dq * 8], aap + (size_t)(64 + r) * DD + dq * 8);
        }
        if (tid < 16) cp_async4(&Smask[1][tid * 4], mp + 64 + tid * 4);
        cp_commit();
    }

    float m0 = -INFINITY, m1 = -INFINITY, s0 = 0.f, s1 = 0.f;
    const int g = lane >> 2, t2 = (lane & 3) * 2;

    for (int jc = 0; jc < 8; jc++) {
        const int buf = jc & 1;
        const unsigned bufu = aa_u + buf * (64 * ISD * 2);

        float c[8][4];
#pragma unroll
        for (int ni = 0; ni < 8; ni++)
#pragma unroll
            for (int e = 0; e < 4; e++) c[ni][e] = 0.f;

#pragma unroll
        for (int kks = 0; kks < 4; kks++) {
            unsigned bf4[4][4];
#pragma unroll
            for (int nn = 0; nn < 4; nn++)
                ldsm_x4(bf4[nn], bufu + ((nn * 16 + lr) * ISD + kks * 16 + ko) * 2);
            // non-trans delivery on [n][k] tile:
            // r0=(n0-7,k0-7) r1=(n8-15,k0-7) r2=(n0-7,k8-15) r3=(n8-15,k8-15)
            // B-frag for n0-7  = {r0, r2};  for n8-15 = {r1, r3}
#pragma unroll
            for (int nn = 0; nn < 4; nn++) {
                mma_bf16_2(c[nn * 2],     a[kks], bf4[nn][0], bf4[nn][2]);
                mma_bf16_2(c[nn * 2 + 1], a[kks], bf4[nn][1], bf4[nn][3]);
            }
        }

        const unsigned char* mk = Smask[buf];
#pragma unroll
        for (int ni = 0; ni < 8; ni++) {
            unsigned char k0 = mk[ni * 8 + t2];
            unsigned char k1 = mk[ni * 8 + t2 + 1];
            if (k0) { c[ni][0] = -3.0e38f; c[ni][2] = -3.0e38f; }
            if (k1) { c[ni][1] = -3.0e38f; c[ni][3] = -3.0e38f; }
        }

        float mx0 = -INFINITY, mx1 = -INFINITY;
#pragma unroll
        for (int ni = 0; ni < 8; ni++) {
            mx0 = fmaxf(mx0, fmaxf(c[ni][0], c[ni][1]));
            mx1 = fmaxf(mx1, fmaxf(c[ni][2], c[ni][3]));
        }
        mx0 = fmaxf(mx0, __shfl_xor_sync(0xffffffffu, mx0, 1));
        mx0 = fmaxf(mx0, __shfl_xor_sync(0xffffffffu, mx0, 2));
        mx1 = fmaxf(mx1, __shfl_xor_sync(0xffffffffu, mx1, 1));
        mx1 = fmaxf(mx1, __shfl_xor_sync(0xffffffffu, mx1, 2));
        float mn0 = fmaxf(m0, mx0), mn1 = fmaxf(m1, mx1);
        float sum0 = 0.f, sum1 = 0.f;
#pragma unroll
        for (int ni = 0; ni < 8; ni++) {
            sum0 += __expf(c[ni][0] - mn0) + __expf(c[ni][1] - mn0);
            sum1 += __expf(c[ni][2] - mn1) + __expf(c[ni][3] - mn1);
        }
        sum0 += __shfl_xor_sync(0xffffffffu, sum0, 1);
        sum0 += __shfl_xor_sync(0xffffffffu, sum0, 2);
        sum1 += __shfl_xor_sync(0xffffffffu, sum1, 1);
        sum1 += __shfl_xor_sync(0xffffffffu, sum1, 2);
        s0 = s0 * __expf(m0 - mn0) + sum0;  m0 = mn0;
        s1 = s1 * __expf(m1 - mn1) + sum1;  m1 = mn1;

        if (jc < 7) {
            cp_wait<0>();
            __syncthreads();
            if (jc + 2 < 8) {
#pragma unroll
                for (int i = 0; i < 2; i++) {
                    int idx = tid + i * 256;
                    int r = idx >> 3, dq = idx & 7;
                    cp_async16(&Saa[buf][r * ISD + dq * 8],
                               aap + (size_t)((jc + 2) * 64 + r) * DD + dq * 8);
                }
                if (tid < 16) cp_async4(&Smask[buf][tid * 4], mp + (jc + 2) * 64 + tid * 4);
                cp_commit();
            }
        }
    }

    if ((lane & 3) == 0) {
        int i0 = itile * 128 + w * 16 + g;
        g_inter[((size_t)b * NQ + i0) * HH + h] = m0 + logf(s0);
        g_inter[((size_t)b * NQ + i0 + 8) * HH + h] = m1 + logf(s1);
    }
}

// ---------------- kernel 4a: fold gating + pred_w into v[b][h] ----------------
__global__ void __launch_bounds__(1024)
gate_kernel(const float* __restrict__ ctx, const float* __restrict__ ctx_w,
            const float* __restrict__ ctx_b, const float* __restrict__ tlw,
            const float* __restrict__ pred_w)
{
    int b = blockIdx.x;
    int h = threadIdx.x >> 5, hp = threadIdx.x & 31;
    const float* cb = ctx + b * CTXD;
    int col = h * 32 + hp;
    float acc = 0.f;
#pragma unroll 8
    for (int k = 0; k < CTXD; k++) acc += cb[k] * ctx_w[k * (HH * HH) + col];
    float g = 1.f / (1.f + expf(-(acc + ctx_b[col])));
    float val = tlw[h * 32 + hp] * g * pred_w[hp];
#pragma unroll
    for (int o = 16; o; o >>= 1) val += __shfl_xor_sync(0xffffffffu, val, o);
    if (hp == 0) g_v[b * HH + h] = val;
}

// ---------------- kernel 4b: pred = softplus(inter . v + pred_b) ----------------
__global__ void pred_kernel(const float* __restrict__ pred_b, float* __restrict__ out)
{
    int idx = blockIdx.x * blockDim.x + threadIdx.x;
    if (idx >= SEQ_ROWS) return;
    int b = idx / NQ;
    const float* ip = g_inter + (size_t)idx * HH;
    const float* vp = g_v + b * HH;
    float x = pred_b[0];
#pragma unroll
    for (int hq = 0; hq < HH; hq++) x += ip[hq] * vp[hq];
    out[idx] = fmaxf(x, 0.f) + log1pf(expf(-fabsf(x)));
}

// ---------------- launch ----------------
extern "C" void kernel_launch(void* const* d_in, const int* in_sizes, int n_in,
                              void* d_out, int out_size)
{
    const float* seq_embed = (const float*)d_in[0];
    const float* aa_embed  = (const float*)d_in[1];
    const float* ctx       = (const float*)d_in[2];
    const float* seq_b     = (const float*)d_in[4];
    const float* aa_b      = (const float*)d_in[6];
    const float* tlw       = (const float*)d_in[7];
    const float* ctx_w     = (const float*)d_in[8];
    const float* ctx_b     = (const float*)d_in[9];
    const float* pred_w    = (const float*)d_in[10];
    const float* pred_b    = (const float*)d_in[11];
    float* out = (float*)d_out;

    cudaFuncSetAttribute(proj_mma_kernel, cudaFuncAttributeMaxDynamicSharedMemorySize,
                         PROJ_SMEM_BYTES);

    cvt_all<<<(CVT_TOT + 255) / 256, 256>>>((const float4*)seq_embed, (const float4*)aa_embed,
                                            (const float4*)d_in[3], (const float4*)d_in[5]);

    mask_detect<<<1, 1>>>((const unsigned int*)d_in[12]);
    mask_canon<<<(BQ * MQ + 255) / 256, 256>>>(d_in[12]);

    proj_mma_kernel<<<dim3(SEQ_ROWS / PT_M, INNER / PT_N), 256, PROJ_SMEM_BYTES>>>(seq_b, 0);
    proj_mma_kernel<<<dim3(AA_ROWS / PT_M, INNER / PT_N), 256, PROJ_SMEM_BYTES>>>(aa_b, 1);

    inter_kernel<<<dim3(NQ / 128, BQ * HH), 256>>>();

    gate_kernel<<<BQ, 1024>>>(ctx, ctx_w, ctx_b, tlw, pred_w);
    pred_kernel<<<(SEQ_ROWS + 255) / 256, 256>>>(pred_b, out);
}